// round 2
// baseline (speedup 1.0000x reference)
#include <cuda_runtime.h>

#define BB 16
#define HH 512
#define WW 512
#define PL (HH*WW)           // 262144 elems per channel plane
#define NPIX (BB*PL)         // 4194304 pixels per input set

// Scratch (static __device__ arrays — no dynamic allocation allowed)
__device__ float g_ssd0[NPIX];   // ssd for source
__device__ float g_ssd1[NPIX];   // ssd for target
__device__ double g_sum[2];      // sum of ssd per input
__device__ double g_loss;        // sum of squared mind diffs (channel 0 only)

__device__ __forceinline__ int clampi(int v, int lo, int hi) {
    return min(max(v, lo), hi);
}

__global__ void k_init() {
    g_sum[0] = 0.0; g_sum[1] = 0.0; g_loss = 0.0;
}

// Pass 1: diff^2 -> 5x5 edge-padded avg pool -> ssd, plus global sum of ssd.
// One block = one 32x32 output tile of one image of one input set.
// grid: (16, 16, 32)  z = which*16 + b ; block: (32, 8)
__global__ __launch_bounds__(256) void k_pass1(const float* __restrict__ src,
                                               const float* __restrict__ tgt) {
    __shared__ float s_d2[36][40];   // diff^2 with +-2 halo (padded stride)
    __shared__ float s_h[36][33];    // horizontal 5-sums
    __shared__ float s_red[8];

    const int tz    = blockIdx.z;
    const int which = tz >> 4;       // 0 = source, 1 = target
    const int b     = tz & 15;
    const float* img = (which ? tgt : src) + (size_t)b * 4 * PL;
    const float* __restrict__ I0 = img;
    const float* __restrict__ I1 = img + PL;
    const float* __restrict__ I2 = img + 2 * PL;
    float* ssd_out = (which ? g_ssd1 : g_ssd0) + (size_t)b * PL;

    const int tx0 = blockIdx.x * 32;
    const int ty0 = blockIdx.y * 32;
    const int t   = threadIdx.y * 32 + threadIdx.x;

    // ---- Stage A: diff^2 over the 36x36 halo region ----
    // Entry (ty,tx) holds diff at the edge-clamped pixel clamp(ty0-2+ty), clamp(tx0-2+tx).
    for (int i = t; i < 36 * 36; i += 256) {
        int ty = i / 36, tx = i - ty * 36;
        int cy = clampi(ty0 - 2 + ty, 0, HH - 1);
        int cx = clampi(tx0 - 2 + tx, 0, WW - 1);
        int ym = max(cy - 2, 0), yp = min(cy + 2, HH - 1);
        int xm = max(cx - 2, 0), xp = min(cx + 2, WW - 1);
        int i_y0xm = cy * WW + xm;
        int i_ypxp = yp * WW + xp;
        int i_ypxm = yp * WW + xm;
        int i_ymx0 = ym * WW + cx;
        float d = I0[i_y0xm] + I0[i_ypxp] + I1[i_ypxm] + I2[i_ypxm]
                - I0[i_ymx0] - I1[i_y0xm] - I2[i_ymx0] - I2[i_ypxp];
        s_d2[ty][tx] = d * d;
    }
    __syncthreads();

    // ---- Stage B: horizontal 5-sum (x edge-clamped), 36 rows x 32 cols ----
    for (int i = t; i < 36 * 32; i += 256) {
        int r = i >> 5, c = i & 31;
        int gx = tx0 + c;
        float s = 0.f;
        #pragma unroll
        for (int dx = -2; dx <= 2; dx++) {
            int sx = clampi(gx + dx, 0, WW - 1) - tx0 + 2;
            s += s_d2[r][sx];
        }
        s_h[r][c] = s;
    }
    __syncthreads();

    // ---- Stage C: vertical 5-sum (y edge-clamped), scale, write, accumulate ----
    float lsum = 0.f;
    const int c = threadIdx.x;
    #pragma unroll
    for (int k = 0; k < 4; k++) {
        int y  = threadIdx.y + k * 8;
        int gy = ty0 + y;
        float s = 0.f;
        #pragma unroll
        for (int dy = -2; dy <= 2; dy++) {
            int sy = clampi(gy + dy, 0, HH - 1) - ty0 + 2;
            s += s_h[sy][c];
        }
        s *= (1.0f / 25.0f);
        ssd_out[gy * WW + tx0 + c] = s;
        lsum += s;
    }

    // block reduction -> double atomic
    #pragma unroll
    for (int o = 16; o; o >>= 1) lsum += __shfl_down_sync(0xffffffffu, lsum, o);
    if (threadIdx.x == 0) s_red[threadIdx.y] = lsum;
    __syncthreads();
    if (t < 8) {
        float v = s_red[t];
        #pragma unroll
        for (int o = 4; o; o >>= 1) v += __shfl_down_sync(0xffu, v, o);
        if (t == 0) atomicAdd(&g_sum[which], (double)v);
    }
}

// Pass 2: clip/exp both ssd arrays, accumulate sum of (m_s - m_t)^2.
__global__ __launch_bounds__(256) void k_pass2() {
    const double inv4N = 1.0 / (4.0 * (double)NPIX);
    const float mv_s = (float)(g_sum[0] * inv4N);
    const float mv_t = (float)(g_sum[1] * inv4N);
    const float lo_s = mv_s * 0.001f, hi_s = mv_s * 1000.0f;
    const float lo_t = mv_t * 0.001f, hi_t = mv_t * 1000.0f;

    float acc = 0.f;
    int stride = gridDim.x * blockDim.x;
    for (int i = blockIdx.x * blockDim.x + threadIdx.x; i < NPIX; i += stride) {
        float a  = g_ssd0[i];
        float va = fminf(fmaxf(a * 0.25f, lo_s), hi_s);
        float ma = __expf(-a / va);          // == exp(-4) exactly when unclipped
        float bt = g_ssd1[i];
        float vb = fminf(fmaxf(bt * 0.25f, lo_t), hi_t);
        float mb = __expf(-bt / vb);
        float d  = ma - mb;
        acc += d * d;
    }

    __shared__ float s_red[8];
    #pragma unroll
    for (int o = 16; o; o >>= 1) acc += __shfl_down_sync(0xffffffffu, acc, o);
    int lane = threadIdx.x & 31, wid = threadIdx.x >> 5;
    if (lane == 0) s_red[wid] = acc;
    __syncthreads();
    if (threadIdx.x < 8) {
        float v = s_red[threadIdx.x];
        #pragma unroll
        for (int o = 4; o; o >>= 1) v += __shfl_down_sync(0xffu, v, o);
        if (threadIdx.x == 0) atomicAdd(&g_loss, (double)v);
    }
}

// Finalize: mean over (B, 3, H, W); channels 1,2 of the output contribute 0.
__global__ void k_final(float* __restrict__ out) {
    out[0] = (float)(g_loss / (3.0 * (double)NPIX));
}

extern "C" void kernel_launch(void* const* d_in, const int* in_sizes, int n_in,
                              void* d_out, int out_size) {
    const float* src = (const float*)d_in[0];
    const float* tgt = (const float*)d_in[1];
    float* out = (float*)d_out;

    k_init<<<1, 1>>>();
    dim3 grid(16, 16, 32), block(32, 8);
    k_pass1<<<grid, block>>>(src, tgt);
    k_pass2<<<2048, 256>>>();
    k_final<<<1, 1>>>(out);
}

// round 3
// speedup vs baseline: 1.6186x; 1.6186x over previous
#include <cuda_runtime.h>

#define BB 16
#define HH 512
#define WW 512
#define PL (HH*WW)           // 262144 elems per channel plane
#define NPIX (BB*PL)         // 4194304 pixels per input set
#define P1_BLOCKS (32*256)   // pass1 total blocks (2 inputs * 16 batches * 16x16 tiles)
#define P2_BLOCKS 2048

// Static scratch (no dynamic allocation allowed)
__device__ float g_ssd0[NPIX];          // ssd for source
__device__ float g_ssd1[NPIX];          // ssd for target
__device__ float g_part1[P1_BLOCKS];    // pass1 per-block partial sums
__device__ float g_part2[P2_BLOCKS];    // pass2 per-block partial sums
__device__ double g_sum[2];             // sum of ssd per input (written by k_mid)

__device__ __forceinline__ int clampi(int v, int lo, int hi) {
    return min(max(v, lo), hi);
}

// ---------------------------------------------------------------------------
// Pass 1: diff^2 -> 5x5 edge-padded avg pool -> ssd, + per-block partial sum.
// One block = one 32x32 output tile. grid (16,16,32), block (32,8).
// ---------------------------------------------------------------------------
__global__ __launch_bounds__(256) void k_pass1(const float* __restrict__ src,
                                               const float* __restrict__ tgt) {
    __shared__ float s_d2[36][40];   // diff^2 with +-2 halo (padded stride)
    __shared__ float s_h[36][33];    // horizontal 5-sums
    __shared__ float s_red[8];

    const int tz    = blockIdx.z;
    const int which = tz >> 4;       // 0 = source, 1 = target
    const int b     = tz & 15;
    const float* img = (which ? tgt : src) + (size_t)b * 4 * PL;
    const float* __restrict__ I0 = img;
    const float* __restrict__ I1 = img + PL;
    const float* __restrict__ I2 = img + 2 * PL;
    float* ssd_out = (which ? g_ssd1 : g_ssd0) + (size_t)b * PL;

    const int bx = blockIdx.x, by = blockIdx.y;
    const int tx0 = bx * 32;
    const int ty0 = by * 32;
    const int t   = threadIdx.y * 32 + threadIdx.x;
    const bool interior = (bx >= 1) && (bx <= 14) && (by >= 1) && (by <= 14);

    // ---- Stage A: diff^2 over the 36x36 halo region ----
    if (interior) {
        #pragma unroll
        for (int i0 = 0; i0 < 36 * 36; i0 += 256 * 2) {
            #pragma unroll
            for (int u = 0; u < 2; u++) {
                int i = i0 + u * 256 + t;
                if (i < 36 * 36) {
                    int ty = i / 36, tx = i - ty * 36;
                    int base = (ty0 - 2 + ty) * WW + (tx0 - 2 + tx);
                    float d = I0[base - 2] + I0[base + 2 * WW + 2]
                            + I1[base + 2 * WW - 2] + I2[base + 2 * WW - 2]
                            - I0[base - 2 * WW] - I1[base - 2]
                            - I2[base - 2 * WW] - I2[base + 2 * WW + 2];
                    s_d2[ty][tx] = d * d;
                }
            }
        }
    } else {
        for (int i = t; i < 36 * 36; i += 256) {
            int ty = i / 36, tx = i - ty * 36;
            int cy = clampi(ty0 - 2 + ty, 0, HH - 1);
            int cx = clampi(tx0 - 2 + tx, 0, WW - 1);
            int ym = max(cy - 2, 0), yp = min(cy + 2, HH - 1);
            int xm = max(cx - 2, 0), xp = min(cx + 2, WW - 1);
            int i_y0xm = cy * WW + xm;
            int i_ypxp = yp * WW + xp;
            int i_ypxm = yp * WW + xm;
            int i_ymx0 = ym * WW + cx;
            float d = I0[i_y0xm] + I0[i_ypxp] + I1[i_ypxm] + I2[i_ypxm]
                    - I0[i_ymx0] - I1[i_y0xm] - I2[i_ymx0] - I2[i_ypxp];
            s_d2[ty][tx] = d * d;
        }
    }
    __syncthreads();

    // ---- Stage B: horizontal 5-sum ----
    if (interior) {
        for (int i = t; i < 36 * 32; i += 256) {
            int r = i >> 5, c = i & 31;
            s_h[r][c] = s_d2[r][c] + s_d2[r][c + 1] + s_d2[r][c + 2]
                      + s_d2[r][c + 3] + s_d2[r][c + 4];
        }
    } else {
        for (int i = t; i < 36 * 32; i += 256) {
            int r = i >> 5, c = i & 31;
            int gx = tx0 + c;
            float s = 0.f;
            #pragma unroll
            for (int dx = -2; dx <= 2; dx++) {
                int sx = clampi(gx + dx, 0, WW - 1) - tx0 + 2;
                s += s_d2[r][sx];
            }
            s_h[r][c] = s;
        }
    }
    __syncthreads();

    // ---- Stage C: vertical 5-sum, scale, write, accumulate ----
    float lsum = 0.f;
    const int c = threadIdx.x;
    #pragma unroll
    for (int k = 0; k < 4; k++) {
        int y  = threadIdx.y + k * 8;
        int gy = ty0 + y;
        float s;
        if (interior) {
            s = s_h[y][c] + s_h[y + 1][c] + s_h[y + 2][c]
              + s_h[y + 3][c] + s_h[y + 4][c];
        } else {
            s = 0.f;
            #pragma unroll
            for (int dy = -2; dy <= 2; dy++) {
                int sy = clampi(gy + dy, 0, HH - 1) - ty0 + 2;
                s += s_h[sy][c];
            }
        }
        s *= (1.0f / 25.0f);
        ssd_out[gy * WW + tx0 + c] = s;
        lsum += s;
    }

    // block reduction -> per-block partial (no atomics)
    #pragma unroll
    for (int o = 16; o; o >>= 1) lsum += __shfl_down_sync(0xffffffffu, lsum, o);
    if (threadIdx.x == 0) s_red[threadIdx.y] = lsum;
    __syncthreads();
    if (t < 8) {
        float v = s_red[t];
        #pragma unroll
        for (int o = 4; o; o >>= 1) v += __shfl_down_sync(0xffu, v, o);
        if (t == 0) g_part1[tz * 256 + by * 16 + bx] = v;
    }
}

// ---------------------------------------------------------------------------
// Mid reduce: 8192 pass1 partials -> g_sum[0], g_sum[1]. One block, 256 thr.
// First half of g_part1 (tz 0..15) is source, second half target.
// ---------------------------------------------------------------------------
__global__ __launch_bounds__(256) void k_mid() {
    __shared__ float s_red[16];
    const int t = threadIdx.x;
    #pragma unroll
    for (int w = 0; w < 2; w++) {
        float acc = 0.f;
        for (int i = t; i < 4096; i += 256) acc += g_part1[w * 4096 + i];
        #pragma unroll
        for (int o = 16; o; o >>= 1) acc += __shfl_down_sync(0xffffffffu, acc, o);
        if ((t & 31) == 0) s_red[(w << 3) | (t >> 5)] = acc;
    }
    __syncthreads();
    if (t < 2) {
        float v = 0.f;
        #pragma unroll
        for (int j = 0; j < 8; j++) v += s_red[(t << 3) | j];
        g_sum[t] = (double)v;
    }
}

// ---------------------------------------------------------------------------
// Pass 2: clip/exp both ssd arrays, per-block partial of (m_s - m_t)^2.
// Only descriptor channel 0 differs between the two images; channels 1..3 of
// the conv are identically zero (kernel builder writes all taps into ch 0),
// so mind channels 1,2 are exp(0)=1 on both sides and cancel.
// ---------------------------------------------------------------------------
__global__ __launch_bounds__(256) void k_pass2() {
    const double inv4N = 1.0 / (4.0 * (double)NPIX);
    const float mv_s = (float)(g_sum[0] * inv4N);
    const float mv_t = (float)(g_sum[1] * inv4N);
    const float lo_s = mv_s * 0.001f, hi_s = mv_s * 1000.0f;
    const float lo_t = mv_t * 0.001f, hi_t = mv_t * 1000.0f;

    const float4* __restrict__ A = (const float4*)g_ssd0;
    const float4* __restrict__ B = (const float4*)g_ssd1;

    float acc = 0.f;
    const int n4 = NPIX / 4;
    const int stride = gridDim.x * blockDim.x;
    for (int i = blockIdx.x * blockDim.x + threadIdx.x; i < n4; i += stride) {
        float4 a4 = A[i];
        float4 b4 = B[i];
        #pragma unroll
        for (int j = 0; j < 4; j++) {
            float a  = (&a4.x)[j];
            float bt = (&b4.x)[j];
            float va = fminf(fmaxf(a * 0.25f, lo_s), hi_s);
            float vb = fminf(fmaxf(bt * 0.25f, lo_t), hi_t);
            float ma = __expf(-a / va);     // == exp(-4) exactly when unclipped
            float mb = __expf(-bt / vb);
            float d  = ma - mb;
            acc += d * d;
        }
    }

    __shared__ float s_red[8];
    #pragma unroll
    for (int o = 16; o; o >>= 1) acc += __shfl_down_sync(0xffffffffu, acc, o);
    int lane = threadIdx.x & 31, wid = threadIdx.x >> 5;
    if (lane == 0) s_red[wid] = acc;
    __syncthreads();
    if (threadIdx.x < 8) {
        float v = s_red[threadIdx.x];
        #pragma unroll
        for (int o = 4; o; o >>= 1) v += __shfl_down_sync(0xffu, v, o);
        if (threadIdx.x == 0) g_part2[blockIdx.x] = v;
    }
}

// ---------------------------------------------------------------------------
// Final: reduce 2048 pass2 partials, write mean over (B, 3, H, W).
// ---------------------------------------------------------------------------
__global__ __launch_bounds__(256) void k_final(float* __restrict__ out) {
    __shared__ float s_red[8];
    const int t = threadIdx.x;
    float acc = 0.f;
    for (int i = t; i < P2_BLOCKS; i += 256) acc += g_part2[i];
    #pragma unroll
    for (int o = 16; o; o >>= 1) acc += __shfl_down_sync(0xffffffffu, acc, o);
    if ((t & 31) == 0) s_red[t >> 5] = acc;
    __syncthreads();
    if (t < 8) {
        float v = s_red[t];
        #pragma unroll
        for (int o = 4; o; o >>= 1) v += __shfl_down_sync(0xffu, v, o);
        if (t == 0) out[0] = (float)((double)v / (3.0 * (double)NPIX));
    }
}

extern "C" void kernel_launch(void* const* d_in, const int* in_sizes, int n_in,
                              void* d_out, int out_size) {
    const float* src = (const float*)d_in[0];
    const float* tgt = (const float*)d_in[1];
    float* out = (float*)d_out;

    dim3 grid(16, 16, 32), block(32, 8);
    k_pass1<<<grid, block>>>(src, tgt);
    k_mid<<<1, 256>>>();
    k_pass2<<<P2_BLOCKS, 256>>>();
    k_final<<<1, 256>>>(out);
}